// round 11
// baseline (speedup 1.0000x reference)
#include <cuda_runtime.h>
#include <cuda_fp16.h>
#include <cuda_pipeline_primitives.h>
#include <mma.h>
#include <stdint.h>

using namespace nvcuda;

// Problem constants (fixed by the dataset)
#define FIN   256
#define FQK   256
#define NQK   (2 * FQK)          // 512
#define MAXN  20000
#define MROWS 20096              // 157 * 128, padded for unguarded tiles
#define SCALING 0.0625f          // FQK^-0.5

// Scratch (no allocation allowed in kernel_launch)
__device__ __half g_qh[(size_t)MROWS * FQK];     // q half, fp16 (scaled)
__device__ __half g_kh[(size_t)MROWS * FQK];     // k half, fp16
__device__ __half g_xh[(size_t)MROWS * FIN];     // x in fp16
__device__ __half g_wh[(size_t)NQK * FIN];       // W in fp16

// ===========================================================================
// Kernel 0: fp32 -> fp16 convert. One thread per float4.
// ===========================================================================
__global__ __launch_bounds__(256)
void convert_kernel(const float* __restrict__ src,
                    __half* __restrict__ dst,
                    int n4)
{
    const int i = blockIdx.x * blockDim.x + threadIdx.x;
    if (i >= n4) return;
    float4 v = ((const float4*)src)[i];
    ((__half2*)dst)[2 * i]     = __halves2half2(__float2half(v.x), __float2half(v.y));
    ((__half2*)dst)[2 * i + 1] = __halves2half2(__float2half(v.z), __float2half(v.w));
}

// ===========================================================================
// Kernel 1: qk = x @ W^T via WMMA fp16. CTA tile 128(m) x 128(n), KC=64,
// 8 warps as 4x2 (warp = 32x64 strip), cp.async double-buffered.
// Output fp16 (q scaled, k plain). (At HMMA floor — unchanged.)
// ===========================================================================
#define BM 128
#define BN 128
#define KC 64
#define LDS_ 72                  // padded smem leading dim (halves)

#define SA_   0
#define SB_   (SA_ + BM * LDS_)              // 9216
#define STAGE_ELEMS (SB_ + BN * LDS_)        // 18432 halves = 36864 B
#define SM_BYTES (STAGE_ELEMS * 2 * 2)       // 73728 B

__device__ __forceinline__ void load_stage(__half* sm,
                                           const __half* __restrict__ xh,
                                           const __half* __restrict__ wh,
                                           int m0, int n0, int kc, int tid)
{
#pragma unroll
    for (int i = 0; i < 4; ++i) {
        const int idx = tid + i * 256;           // 0..1023
        const int r = idx >> 3;                  // 0..127
        const int c = (idx & 7) * 8;             // 0..56
        const size_t g = (size_t)(m0 + r) * FIN + kc + c;
        __pipeline_memcpy_async(sm + SA_ + r * LDS_ + c, xh + g, 16);
    }
#pragma unroll
    for (int i = 0; i < 4; ++i) {
        const int idx = tid + i * 256;
        const int r = idx >> 3;
        const int c = (idx & 7) * 8;
        const size_t g = (size_t)(n0 + r) * FIN + kc + c;
        __pipeline_memcpy_async(sm + SB_ + r * LDS_ + c, wh + g, 16);
    }
}

__global__ __launch_bounds__(256)
void gemm_qk_wmma(const __half* __restrict__ xh,
                  const __half* __restrict__ wh,
                  __half* __restrict__ qout,
                  __half* __restrict__ kout)
{
    extern __shared__ __half sm[];
    const int tid = threadIdx.x;
    const int wid = tid >> 5;
    const int lane = tid & 31;
    const int warp_m = wid >> 1;          // 0..3
    const int warp_n = wid & 1;           // 0..1
    const int m0  = blockIdx.y * BM;
    const int n0  = blockIdx.x * BN;
    const bool is_q = (n0 < FQK);
    const float scale = is_q ? SCALING : 1.0f;

    wmma::fragment<wmma::accumulator, 16, 16, 16, float> acc[2][4];
#pragma unroll
    for (int mi = 0; mi < 2; ++mi)
#pragma unroll
        for (int f = 0; f < 4; ++f) wmma::fill_fragment(acc[mi][f], 0.0f);

    load_stage(sm, xh, wh, m0, n0, 0, tid);
    __pipeline_commit();
    load_stage(sm + STAGE_ELEMS, xh, wh, m0, n0, KC, tid);
    __pipeline_commit();

    const int nChunks = FIN / KC;   // 4
    for (int c = 0; c < nChunks; ++c) {
        __pipeline_wait_prior(1);
        __syncthreads();
        __half* st = sm + (c & 1) * STAGE_ELEMS;

#pragma unroll
        for (int ks = 0; ks < KC / 16; ++ks) {
            wmma::fragment<wmma::matrix_a, 16, 16, 16, __half, wmma::row_major> ah[2];
#pragma unroll
            for (int mi = 0; mi < 2; ++mi) {
                const int row = warp_m * 32 + mi * 16;
                wmma::load_matrix_sync(ah[mi], st + SA_ + row * LDS_ + ks * 16, LDS_);
            }
#pragma unroll
            for (int nf = 0; nf < 4; ++nf) {
                const int col = warp_n * 64 + nf * 16;
                wmma::fragment<wmma::matrix_b, 16, 16, 16, __half, wmma::col_major> bh;
                wmma::load_matrix_sync(bh, st + SB_ + col * LDS_ + ks * 16, LDS_);
#pragma unroll
                for (int mi = 0; mi < 2; ++mi)
                    wmma::mma_sync(acc[mi][nf], ah[mi], bh, acc[mi][nf]);
            }
        }
        __syncthreads();
        if (c + 2 < nChunks) {
            load_stage(st, xh, wh, m0, n0, (c + 2) * KC, tid);
        }
        __pipeline_commit();
    }

    // ---- epilogue: fp32 acc -> fp16 via per-warp smem scratch ----
    __syncthreads();
    float* buf = (float*)sm + wid * (16 * 64);   // 4 KB per warp
    __half* outp = is_q ? qout : kout;
    const int col0 = (is_q ? n0 : n0 - FQK) + warp_n * 64;

#pragma unroll
    for (int mi = 0; mi < 2; ++mi) {
        const int row0 = m0 + warp_m * 32 + mi * 16;
#pragma unroll
        for (int nf = 0; nf < 4; ++nf) {
#pragma unroll
            for (int t = 0; t < acc[mi][nf].num_elements; ++t)
                acc[mi][nf].x[t] *= scale;
            wmma::store_matrix_sync(buf + nf * 16, acc[mi][nf], 64, wmma::mem_row_major);
        }
        __syncwarp();
#pragma unroll
        for (int r = 0; r < 16; ++r) {
            float a = buf[r * 64 + 2 * lane];
            float b = buf[r * 64 + 2 * lane + 1];
            ((__half2*)(outp + (size_t)(row0 + r) * FQK + col0))[lane] =
                __halves2half2(__float2half(a), __float2half(b));
        }
        __syncwarp();
    }
}

// ===========================================================================
// Kernel 2: fused edge pass. One warp per src node; 8 lanes per edge,
// 4 edges per iteration. k rows staged through a per-warp cp.async SMEM
// ring, now 4 STAGES deep (wait_prior(3) => 3 stage-fills in flight,
// ~510 cyc of latency cover). Dynamic smem: 64KB ring + 4KB exbuf.
// ===========================================================================
#define SMEM_DEG 128
#define NSTG 4
// per-warp ring: NSTG stages x 4 rows x 256 halves = 8 KB
#define WARP_RING_HALVES (NSTG * 4 * 256)
#define EDGE_SM_BYTES (8 * WARP_RING_HALVES * 2 + 8 * SMEM_DEG * 4)  // 69632

__device__ __forceinline__ int lower_bound_i(const int* __restrict__ a,
                                             int n, int v)
{
    int lo = 0, hi = n;
    while (lo < hi) {
        int mid = (lo + hi) >> 1;
        if (a[mid] < v) lo = mid + 1; else hi = mid;
    }
    return lo;
}

// dot of 4 uint4 (32 halves) q x k per lane; 4 indep half2 accumulators
__device__ __forceinline__ float dot_h8(const uint4* q, const uint4* k)
{
    const __half2* qh = (const __half2*)q;
    const __half2* kh2 = (const __half2*)k;
    __half2 a0 = __hmul2(qh[0], kh2[0]);
    __half2 a1 = __hmul2(qh[1], kh2[1]);
    __half2 a2 = __hmul2(qh[2], kh2[2]);
    __half2 a3 = __hmul2(qh[3], kh2[3]);
#pragma unroll
    for (int i = 1; i < 4; ++i) {
        a0 = __hfma2(qh[4 * i + 0], kh2[4 * i + 0], a0);
        a1 = __hfma2(qh[4 * i + 1], kh2[4 * i + 1], a1);
        a2 = __hfma2(qh[4 * i + 2], kh2[4 * i + 2], a2);
        a3 = __hfma2(qh[4 * i + 3], kh2[4 * i + 3], a3);
    }
    float2 f0 = __half22float2(a0);
    float2 f1 = __half22float2(a1);
    float2 f2 = __half22float2(a2);
    float2 f3 = __half22float2(a3);
    return ((f0.x + f0.y) + (f1.x + f1.y)) + ((f2.x + f2.y) + (f3.x + f3.y));
}

// fill one 4-row stage: each lane copies 16B per row (32 lanes = 512B row)
__device__ __forceinline__ void fill_stage(__half* dst,          // [4][256]
                                           const __half* __restrict__ kh,
                                           const int* __restrict__ dest,
                                           int j0, int hi, int lane)
{
#pragma unroll
    for (int r = 0; r < 4; ++r) {
        int j = j0 + r;
        if (j >= hi) j = hi - 1;
        const __half* src = kh + (size_t)dest[j] * FQK;
        __pipeline_memcpy_async(dst + r * 256 + lane * 8, src + lane * 8, 16);
    }
}

__global__ __launch_bounds__(256)
void edge_fused_kernel(const int* __restrict__ ei,
                       const __half* __restrict__ qh,
                       const __half* __restrict__ kh,
                       float* __restrict__ out,
                       int E, int N)
{
    extern __shared__ char esm[];
    const int wslot = threadIdx.x >> 5;
    __half* kwarp = (__half*)esm + (size_t)wslot * WARP_RING_HALVES;
    float*  exbuf = (float*)(esm + 8 * WARP_RING_HALVES * 2) + wslot * SMEM_DEG;

    const int node  = (blockIdx.x * blockDim.x + threadIdx.x) >> 5;
    const int lane  = threadIdx.x & 31;
    const int g     = lane >> 3;          // edge slot 0..3
    const int u     = lane & 7;           // chunk owner within 8-lane group
    if (node >= N) return;

    const int lo = lower_bound_i(ei, E, node);
    const int hi = lower_bound_i(ei, E, node + 1);
    const int deg = hi - lo;
    if (deg <= 0) return;

    // lane u owns uint4s {u, u+8, u+16, u+24} of the 32-uint4 q row
    const uint4* qp = (const uint4*)(qh + (size_t)node * FQK);
    uint4 qr[4];
#pragma unroll
    for (int i = 0; i < 4; ++i) qr[i] = qp[u + 8 * i];

    const int* __restrict__ dest = ei + E;
    const int nIter = (deg + 3) >> 2;
    const bool in_smem = (deg <= SMEM_DEG);
    float* exdst = in_smem ? exbuf : &out[lo];
    float sum = 0.0f;

    // prologue: fill all NSTG stages
#pragma unroll
    for (int s = 0; s < NSTG; ++s) {
        fill_stage(kwarp + s * 1024, kh, dest, lo + 4 * s, hi, lane);
        __pipeline_commit();
    }

    for (int it = 0; it < nIter; ++it) {
        __pipeline_wait_prior(NSTG - 1);
        __syncwarp();

        // group g consumes row g of the oldest stage
        const int st = it & (NSTG - 1);
        const uint4* rp = (const uint4*)(kwarp + st * 1024 + g * 256);
        uint4 cr[4];
#pragma unroll
        for (int i = 0; i < 4; ++i) cr[i] = rp[u + 8 * i];

        __syncwarp();   // all reads done before the stage is refilled
        fill_stage(kwarp + st * 1024, kh, dest, lo + 4 * (it + NSTG), hi, lane);
        __pipeline_commit();

        float p = dot_h8(qr, cr);
#pragma unroll
        for (int o = 1; o < 8; o <<= 1)
            p += __shfl_xor_sync(0xffffffffu, p, o);

        const int j = lo + 4 * it + g;
        if (j < hi) {
            float ex = __expf(p);
            sum += ex;
            if (u == 0) exdst[j - lo] = ex;
        }
    }

    // combine the four group sums (deterministic order)
    sum += __shfl_xor_sync(0xffffffffu, sum, 8);
    sum += __shfl_xor_sync(0xffffffffu, sum, 16);
    const float inv = 1.0f / sum;

    if (in_smem) {
        __syncwarp();
        for (int i = lane; i < deg; i += 32)
            out[lo + i] = exbuf[i] * inv;
    } else {
        __threadfence_block();
        __syncwarp();
        for (int i = lane; i < deg; i += 32)
            out[lo + i] *= inv;
    }
}

// ===========================================================================
extern "C" void kernel_launch(void* const* d_in, const int* in_sizes, int n_in,
                              void* d_out, int out_size)
{
    const float* x   = (const float*)d_in[0];
    const int*   ei  = (const int*)d_in[1];
    const float* W   = (const float*)d_in[2];
    float*       out = (float*)d_out;

    const int N = in_sizes[0] / FIN;     // 20000
    const int E = in_sizes[1] / 2;       // 640000

    __half* qht; cudaGetSymbolAddress((void**)&qht, g_qh);
    __half* kht; cudaGetSymbolAddress((void**)&kht, g_kh);
    __half* xh;  cudaGetSymbolAddress((void**)&xh,  g_xh);
    __half* wh;  cudaGetSymbolAddress((void**)&wh,  g_wh);

    // 0) convert x, W -> fp16
    {
        int n4x = N * FIN / 4;
        convert_kernel<<<(n4x + 255) / 256, 256>>>(x, xh, n4x);
        int n4w = NQK * FIN / 4;
        convert_kernel<<<(n4w + 255) / 256, 256>>>(W, wh, n4w);
    }
    // 1) projection GEMM (fp16 WMMA, cp.async double-buffered)
    {
        cudaFuncSetAttribute(gemm_qk_wmma,
                             cudaFuncAttributeMaxDynamicSharedMemorySize,
                             SM_BYTES);
        dim3 grid(NQK / BN, MROWS / BM);
        gemm_qk_wmma<<<grid, 256, SM_BYTES>>>(xh, wh, qht, kht);
    }
    // 2) fused edge dot + scatter softmax (one warp per node, 4-stage ring)
    {
        cudaFuncSetAttribute(edge_fused_kernel,
                             cudaFuncAttributeMaxDynamicSharedMemorySize,
                             EDGE_SM_BYTES);
        int blocks = (N * 32 + 255) / 256;
        edge_fused_kernel<<<blocks, 256, EDGE_SM_BYTES>>>(ei, qht, kht, out, E, N);
    }
}

// round 12
// speedup vs baseline: 1.3481x; 1.3481x over previous
#include <cuda_runtime.h>
#include <cuda_fp16.h>
#include <cuda_pipeline_primitives.h>
#include <mma.h>
#include <stdint.h>

using namespace nvcuda;

// Problem constants (fixed by the dataset)
#define FIN   256
#define FQK   256
#define NQK   (2 * FQK)          // 512
#define MAXN  20000
#define MROWS 20096              // 157 * 128, padded for unguarded tiles
#define SCALING 0.0625f          // FQK^-0.5

// Scratch (no allocation allowed in kernel_launch)
__device__ __half g_qh[(size_t)MROWS * FQK];     // q half, fp16 (scaled)
__device__ __half g_kh[(size_t)MROWS * FQK];     // k half, fp16
__device__ __half g_xh[(size_t)MROWS * FIN];     // x in fp16
__device__ __half g_wh[(size_t)NQK * FIN];       // W in fp16
__device__ int    g_rowptr[MAXN + 1];            // CSR row offsets

// ===========================================================================
// Kernel 0: fp32 -> fp16 convert. One thread per float4.
// ===========================================================================
__global__ __launch_bounds__(256)
void convert_kernel(const float* __restrict__ src,
                    __half* __restrict__ dst,
                    int n4)
{
    const int i = blockIdx.x * blockDim.x + threadIdx.x;
    if (i >= n4) return;
    float4 v = ((const float4*)src)[i];
    ((__half2*)dst)[2 * i]     = __halves2half2(__float2half(v.x), __float2half(v.y));
    ((__half2*)dst)[2 * i + 1] = __halves2half2(__float2half(v.z), __float2half(v.w));
}

// ===========================================================================
// Kernel 0c: rowptr[v] = lower_bound(src, v) via boundary scan over sorted src.
// ===========================================================================
__global__ __launch_bounds__(256)
void rowptr_kernel(const int* __restrict__ src,
                   int* __restrict__ rowptr,
                   int E, int N)
{
    const int e = blockIdx.x * blockDim.x + threadIdx.x;
    if (e >= E) return;
    const int s = src[e];
    if (e == 0) {
        for (int v = 0; v <= s; ++v) rowptr[v] = 0;
    } else {
        const int sp = src[e - 1];
        for (int v = sp + 1; v <= s; ++v) rowptr[v] = e;
    }
    if (e == E - 1) {
        for (int v = s + 1; v <= N; ++v) rowptr[v] = E;
    }
}

// ===========================================================================
// Kernel 1: qk = x @ W^T via WMMA fp16. CTA tile 128(m) x 128(n), KC=64,
// 8 warps as 4x2 (warp = 32x64 strip), cp.async double-buffered.
// Output fp16 (q scaled, k plain). (At HMMA floor — unchanged.)
// ===========================================================================
#define BM 128
#define BN 128
#define KC 64
#define LDS_ 72                  // padded smem leading dim (halves)

#define SA_   0
#define SB_   (SA_ + BM * LDS_)              // 9216
#define STAGE_ELEMS (SB_ + BN * LDS_)        // 18432 halves = 36864 B
#define SM_BYTES (STAGE_ELEMS * 2 * 2)       // 73728 B

__device__ __forceinline__ void load_stage(__half* sm,
                                           const __half* __restrict__ xh,
                                           const __half* __restrict__ wh,
                                           int m0, int n0, int kc, int tid)
{
#pragma unroll
    for (int i = 0; i < 4; ++i) {
        const int idx = tid + i * 256;           // 0..1023
        const int r = idx >> 3;                  // 0..127
        const int c = (idx & 7) * 8;             // 0..56
        const size_t g = (size_t)(m0 + r) * FIN + kc + c;
        __pipeline_memcpy_async(sm + SA_ + r * LDS_ + c, xh + g, 16);
    }
#pragma unroll
    for (int i = 0; i < 4; ++i) {
        const int idx = tid + i * 256;
        const int r = idx >> 3;
        const int c = (idx & 7) * 8;
        const size_t g = (size_t)(n0 + r) * FIN + kc + c;
        __pipeline_memcpy_async(sm + SB_ + r * LDS_ + c, wh + g, 16);
    }
}

__global__ __launch_bounds__(256)
void gemm_qk_wmma(const __half* __restrict__ xh,
                  const __half* __restrict__ wh,
                  __half* __restrict__ qout,
                  __half* __restrict__ kout)
{
    extern __shared__ __half sm[];
    const int tid = threadIdx.x;
    const int wid = tid >> 5;
    const int lane = tid & 31;
    const int warp_m = wid >> 1;          // 0..3
    const int warp_n = wid & 1;           // 0..1
    const int m0  = blockIdx.y * BM;
    const int n0  = blockIdx.x * BN;
    const bool is_q = (n0 < FQK);
    const float scale = is_q ? SCALING : 1.0f;

    wmma::fragment<wmma::accumulator, 16, 16, 16, float> acc[2][4];
#pragma unroll
    for (int mi = 0; mi < 2; ++mi)
#pragma unroll
        for (int f = 0; f < 4; ++f) wmma::fill_fragment(acc[mi][f], 0.0f);

    load_stage(sm, xh, wh, m0, n0, 0, tid);
    __pipeline_commit();
    load_stage(sm + STAGE_ELEMS, xh, wh, m0, n0, KC, tid);
    __pipeline_commit();

    const int nChunks = FIN / KC;   // 4
    for (int c = 0; c < nChunks; ++c) {
        __pipeline_wait_prior(1);
        __syncthreads();
        __half* st = sm + (c & 1) * STAGE_ELEMS;

#pragma unroll
        for (int ks = 0; ks < KC / 16; ++ks) {
            wmma::fragment<wmma::matrix_a, 16, 16, 16, __half, wmma::row_major> ah[2];
#pragma unroll
            for (int mi = 0; mi < 2; ++mi) {
                const int row = warp_m * 32 + mi * 16;
                wmma::load_matrix_sync(ah[mi], st + SA_ + row * LDS_ + ks * 16, LDS_);
            }
#pragma unroll
            for (int nf = 0; nf < 4; ++nf) {
                const int col = warp_n * 64 + nf * 16;
                wmma::fragment<wmma::matrix_b, 16, 16, 16, __half, wmma::col_major> bh;
                wmma::load_matrix_sync(bh, st + SB_ + col * LDS_ + ks * 16, LDS_);
#pragma unroll
                for (int mi = 0; mi < 2; ++mi)
                    wmma::mma_sync(acc[mi][nf], ah[mi], bh, acc[mi][nf]);
            }
        }
        __syncthreads();
        if (c + 2 < nChunks) {
            load_stage(st, xh, wh, m0, n0, (c + 2) * KC, tid);
        }
        __pipeline_commit();
    }

    // ---- epilogue: fp32 acc -> fp16 via per-warp smem scratch ----
    __syncthreads();
    float* buf = (float*)sm + wid * (16 * 64);   // 4 KB per warp
    __half* outp = is_q ? qout : kout;
    const int col0 = (is_q ? n0 : n0 - FQK) + warp_n * 64;

#pragma unroll
    for (int mi = 0; mi < 2; ++mi) {
        const int row0 = m0 + warp_m * 32 + mi * 16;
#pragma unroll
        for (int nf = 0; nf < 4; ++nf) {
#pragma unroll
            for (int t = 0; t < acc[mi][nf].num_elements; ++t)
                acc[mi][nf].x[t] *= scale;
            wmma::store_matrix_sync(buf + nf * 16, acc[mi][nf], 64, wmma::mem_row_major);
        }
        __syncwarp();
#pragma unroll
        for (int r = 0; r < 16; ++r) {
            float a = buf[r * 64 + 2 * lane];
            float b = buf[r * 64 + 2 * lane + 1];
            ((__half2*)(outp + (size_t)(row0 + r) * FQK + col0))[lane] =
                __halves2half2(__float2half(a), __float2half(b));
        }
        __syncwarp();
    }
}

// ===========================================================================
// Kernel 2: fused edge pass (round-10 winner + precomputed rowptr).
// One warp per src node; 8 lanes per edge, 4 edges per iteration;
// 2-stage x 4-row cp.async ring in static smem.
// ===========================================================================
#define SMEM_DEG 128

// dot of 4 uint4 (32 halves) q x k per lane; 4 indep half2 accumulators
__device__ __forceinline__ float dot_h8(const uint4* q, const uint4* k)
{
    const __half2* qh = (const __half2*)q;
    const __half2* kh2 = (const __half2*)k;
    __half2 a0 = __hmul2(qh[0], kh2[0]);
    __half2 a1 = __hmul2(qh[1], kh2[1]);
    __half2 a2 = __hmul2(qh[2], kh2[2]);
    __half2 a3 = __hmul2(qh[3], kh2[3]);
#pragma unroll
    for (int i = 1; i < 4; ++i) {
        a0 = __hfma2(qh[4 * i + 0], kh2[4 * i + 0], a0);
        a1 = __hfma2(qh[4 * i + 1], kh2[4 * i + 1], a1);
        a2 = __hfma2(qh[4 * i + 2], kh2[4 * i + 2], a2);
        a3 = __hfma2(qh[4 * i + 3], kh2[4 * i + 3], a3);
    }
    float2 f0 = __half22float2(a0);
    float2 f1 = __half22float2(a1);
    float2 f2 = __half22float2(a2);
    float2 f3 = __half22float2(a3);
    return ((f0.x + f0.y) + (f1.x + f1.y)) + ((f2.x + f2.y) + (f3.x + f3.y));
}

// fill one 4-row stage: lane copies 16B per row (32 lanes cover 512B row)
__device__ __forceinline__ void fill_stage(__half (*dst)[256],
                                           const __half* __restrict__ kh,
                                           const int* __restrict__ dest,
                                           int j0, int hi, int lane)
{
#pragma unroll
    for (int r = 0; r < 4; ++r) {
        int j = j0 + r;
        if (j >= hi) j = hi - 1;
        const __half* src = kh + (size_t)dest[j] * FQK;
        __pipeline_memcpy_async(&dst[r][lane * 8], src + lane * 8, 16);
    }
}

__global__ __launch_bounds__(256)
void edge_fused_kernel(const int* __restrict__ ei,
                       const int* __restrict__ rowptr,
                       const __half* __restrict__ qh,
                       const __half* __restrict__ kh,
                       float* __restrict__ out,
                       int E, int N)
{
    // per-warp: 2 stages x 4 rows x 256 halves = 4 KB ring + 512 B exbuf
    __shared__ __half kbuf[8][2][4][256];       // 32 KB
    __shared__ float exbuf[8][SMEM_DEG];        // 4 KB

    const int wslot = threadIdx.x >> 5;
    const int node  = (blockIdx.x * blockDim.x + threadIdx.x) >> 5;
    const int lane  = threadIdx.x & 31;
    const int g     = lane >> 3;          // edge slot 0..3
    const int u     = lane & 7;           // chunk owner within 8-lane group
    if (node >= N) return;

    const int lo = rowptr[node];
    const int hi = rowptr[node + 1];
    const int deg = hi - lo;
    if (deg <= 0) return;

    // lane u owns uint4s {u, u+8, u+16, u+24} of the 32-uint4 q row
    const uint4* qp = (const uint4*)(qh + (size_t)node * FQK);
    uint4 qr[4];
#pragma unroll
    for (int i = 0; i < 4; ++i) qr[i] = qp[u + 8 * i];

    const int* __restrict__ dest = ei + E;
    const int nIter = (deg + 3) >> 2;
    const bool in_smem = (deg <= SMEM_DEG);
    float* exdst = in_smem ? &exbuf[wslot][0] : &out[lo];
    float sum = 0.0f;

    // prologue: fill both stages
    fill_stage(kbuf[wslot][0], kh, dest, lo, hi, lane);
    __pipeline_commit();
    fill_stage(kbuf[wslot][1], kh, dest, lo + 4, hi, lane);
    __pipeline_commit();

    for (int it = 0; it < nIter; ++it) {
        __pipeline_wait_prior(1);
        __syncwarp();

        // group g consumes row g of the current stage
        const uint4* rp = (const uint4*)kbuf[wslot][it & 1][g];
        uint4 cr[4];
#pragma unroll
        for (int i = 0; i < 4; ++i) cr[i] = rp[u + 8 * i];

        __syncwarp();   // all reads done before the stage is refilled
        fill_stage(kbuf[wslot][it & 1], kh, dest, lo + 4 * (it + 2), hi, lane);
        __pipeline_commit();

        float p = dot_h8(qr, cr);
#pragma unroll
        for (int o = 1; o < 8; o <<= 1)
            p += __shfl_xor_sync(0xffffffffu, p, o);

        const int j = lo + 4 * it + g;
        if (j < hi) {
            float ex = __expf(p);
            sum += ex;
            if (u == 0) exdst[j - lo] = ex;
        }
    }

    // combine the four group sums (deterministic order)
    sum += __shfl_xor_sync(0xffffffffu, sum, 8);
    sum += __shfl_xor_sync(0xffffffffu, sum, 16);
    const float inv = 1.0f / sum;

    if (in_smem) {
        __syncwarp();
        for (int i = lane; i < deg; i += 32)
            out[lo + i] = exbuf[wslot][i] * inv;
    } else {
        __threadfence_block();
        __syncwarp();
        for (int i = lane; i < deg; i += 32)
            out[lo + i] *= inv;
    }
}

// ===========================================================================
extern "C" void kernel_launch(void* const* d_in, const int* in_sizes, int n_in,
                              void* d_out, int out_size)
{
    const float* x   = (const float*)d_in[0];
    const int*   ei  = (const int*)d_in[1];
    const float* W   = (const float*)d_in[2];
    float*       out = (float*)d_out;

    const int N = in_sizes[0] / FIN;     // 20000
    const int E = in_sizes[1] / 2;       // 640000

    __half* qht; cudaGetSymbolAddress((void**)&qht, g_qh);
    __half* kht; cudaGetSymbolAddress((void**)&kht, g_kh);
    __half* xh;  cudaGetSymbolAddress((void**)&xh,  g_xh);
    __half* wh;  cudaGetSymbolAddress((void**)&wh,  g_wh);
    int* rowptr; cudaGetSymbolAddress((void**)&rowptr, g_rowptr);

    // 0) convert x, W -> fp16; build rowptr from sorted src
    {
        int n4x = N * FIN / 4;
        convert_kernel<<<(n4x + 255) / 256, 256>>>(x, xh, n4x);
        int n4w = NQK * FIN / 4;
        convert_kernel<<<(n4w + 255) / 256, 256>>>(W, wh, n4w);
        rowptr_kernel<<<(E + 255) / 256, 256>>>(ei, rowptr, E, N);
    }
    // 1) projection GEMM (fp16 WMMA, cp.async double-buffered)
    {
        cudaFuncSetAttribute(gemm_qk_wmma,
                             cudaFuncAttributeMaxDynamicSharedMemorySize,
                             SM_BYTES);
        dim3 grid(NQK / BN, MROWS / BM);
        gemm_qk_wmma<<<grid, 256, SM_BYTES>>>(xh, wh, qht, kht);
    }
    // 2) fused edge dot + scatter softmax (one warp per node, 2-stage ring)
    {
        int blocks = (N * 32 + 255) / 256;
        edge_fused_kernel<<<blocks, 256>>>(ei, rowptr, qht, kht, out, E, N);
    }
}